// round 17
// baseline (speedup 1.0000x reference)
#include <cuda_runtime.h>
#include <cuda_bf16.h>
#include <math.h>
#include <stdint.h>

// Problem constants
#define E_      8
#define S_      512
#define DIM_    1024
#define DFF_    2730
#define DFF2_   5460
#define VOCAB_  32000
#define NPAIR   1024   // S_ * 2

// ------------------------- device scratch (device-code access only) ----------
__device__ int   g_done;
__device__ int   g_cnt[E_];
__device__ int   g_rows[E_][NPAIR];
__device__ int   g_eid[NPAIR];
__device__ float g_gate[NPAIR];
__device__ unsigned long long g_mlse[NPAIR];   // packed (max:lo32, sum:hi32)
__device__ float g_h1[(size_t)NPAIR * DFF_];
__device__ float g_h2[(size_t)NPAIR * DIM_];
__device__ float g_logits[(size_t)NPAIR * VOCAB_];

// ------------------------- PTX helpers (sm_75/80-era, plain sm_103-safe) -----
__device__ __forceinline__ uint32_t smem_u32(const void* p) {
    uint32_t a;
    asm("{ .reg .u64 t; cvta.to.shared.u64 t, %1; cvt.u32.u64 %0, t; }"
        : "=r"(a) : "l"(p));
    return a;
}
__device__ __forceinline__ uint32_t packbf(float lo, float hi) {
    uint32_t r;
    asm("cvt.rn.bf16x2.f32 %0, %1, %2;" : "=r"(r) : "f"(hi), "f"(lo));
    return r;
}
#define STS64(addr, r0, r1) \
    asm volatile("st.shared.v2.b32 [%0], {%1,%2};" :: "r"(addr), "r"(r0), "r"(r1) : "memory")
#define STS32(addr, r0) \
    asm volatile("st.shared.b32 [%0], %1;" :: "r"(addr), "r"(r0) : "memory")
#define LDSM_X4(r0, r1, r2, r3, addr) \
    asm volatile("ldmatrix.sync.aligned.m8n8.x4.shared.b16 {%0,%1,%2,%3}, [%4];" \
        : "=r"(r0), "=r"(r1), "=r"(r2), "=r"(r3) : "r"(addr))

__device__ __forceinline__ void mma_bf16(float* d, const uint32_t* a, const uint32_t* b) {
    asm volatile(
        "mma.sync.aligned.m16n8k16.row.col.f32.bf16.bf16.f32 "
        "{%0,%1,%2,%3}, {%4,%5,%6,%7}, {%8,%9}, {%0,%1,%2,%3};"
        : "+f"(d[0]), "+f"(d[1]), "+f"(d[2]), "+f"(d[3])
        : "r"(a[0]), "r"(a[1]), "r"(a[2]), "r"(a[3]), "r"(b[0]), "r"(b[1]));
}

// packed online-LSE atomic merge: g_mlse[p] = (m, s) ⊕ (m2, s2)
__device__ __forceinline__ void lse_atomic_merge(int p, float m2, float s2) {
    unsigned long long* a = &g_mlse[p];
    unsigned long long old = *a, assumed;
    do {
        assumed = old;
        float m1 = __uint_as_float((unsigned)(assumed & 0xffffffffull));
        float s1 = __uint_as_float((unsigned)(assumed >> 32));
        float mm = fmaxf(m1, m2);
        float ss = s1 * expf(m1 - mm) + s2 * expf(m2 - mm);
        unsigned long long nv =
            ((unsigned long long)__float_as_uint(ss) << 32) | __float_as_uint(mm);
        old = atomicCAS(a, assumed, nv);
    } while (old != assumed);
}

// ------------------------- router + fused grouping + lse reset ---------------
__global__ void router_kernel(const float* __restrict__ x,
                              const float* __restrict__ Wr) {
    int s = blockIdx.x;
    const float* xr = x + (size_t)s * DIM_;
    float acc[E_];
#pragma unroll
    for (int e = 0; e < E_; e++) acc[e] = 0.f;
    for (int d = threadIdx.x; d < DIM_; d += blockDim.x) {
        float xv = xr[d];
#pragma unroll
        for (int e = 0; e < E_; e++) acc[e] = fmaf(xv, Wr[e * DIM_ + d], acc[e]);
    }
    __shared__ float red[256];
    __shared__ float score[E_];
#pragma unroll
    for (int e = 0; e < E_; e++) {
        red[threadIdx.x] = acc[e];
        __syncthreads();
        for (int st = 128; st > 0; st >>= 1) {
            if (threadIdx.x < st) red[threadIdx.x] += red[threadIdx.x + st];
            __syncthreads();
        }
        if (threadIdx.x == 0) score[e] = red[0];
        __syncthreads();
    }
    if (threadIdx.x == 0) {
        int i0 = 0; float s0 = score[0];
        for (int e = 1; e < E_; e++) if (score[e] > s0) { s0 = score[e]; i0 = e; }
        int i1 = -1; float s1 = -INFINITY;
        for (int e = 0; e < E_; e++) {
            if (e == i0) continue;
            if (score[e] > s1) { s1 = score[e]; i1 = e; }
        }
        float m   = fmaxf(s0, s1);
        float lse = m + logf(expf(s0 - m) + expf(s1 - m));
        int p0 = 2 * s, p1 = 2 * s + 1;
        g_gate[p0] = s0 - lse;  g_gate[p1] = s1 - lse;
        g_eid[p0]  = i0;        g_eid[p1]  = i1;
    }

    __shared__ int amLast;
    __threadfence();
    if (threadIdx.x == 0) {
        int t = atomicAdd(&g_done, 1);
        amLast = (t == S_ - 1) ? 1 : 0;
    }
    __syncthreads();
    if (amLast) {
        __threadfence();
        int w = threadIdx.x / 32, lane = threadIdx.x % 32;
        if (w < E_) {
            int count = 0;
            for (int base = 0; base < NPAIR; base += 32) {
                int p  = base + lane;
                int id = g_eid[p];
                unsigned mask = __ballot_sync(0xffffffffu, id == w);
                if (id == w)
                    g_rows[w][count + __popc(mask & ((1u << lane) - 1u))] = p;
                count += __popc(mask);
            }
            if (lane == 0) g_cnt[w] = count;
        }
        // reset packed LSE accumulators: (m=-INF, s=0)
        const unsigned long long init =
            (unsigned long long)__float_as_uint(-INFINITY);
        for (int i = threadIdx.x; i < NPAIR; i += 256) g_mlse[i] = init;
        if (threadIdx.x == 0) g_done = 0;
        __threadfence();
    }
}

// ------------------------- bf16-smem ldmatrix GEMM --------------------------
// Block tile 128x256, BK=32, 512 threads = 16 warps (2m x 8n), warp tile 64x32.
// Grid: (m-tile, n-tile, expert) — m fastest for L2 reuse of B slabs.
// Single barrier per chunk (double-buffer hazard analysis). LDG before compute.
// mode 0: C = A@W^T (+bias +resid).  mode 1: up+SwiGLU fused.
// do_lse: fused per-row online logsumexp from accumulators (proj only).
#define TM 128
#define TN 256
#define BK 32
#define NTHREADS 512
#define LDH 40
#define A_H (128 * LDH)
#define B_H (256 * LDH)
#define A_BYTES (A_H * 2)
#define STAGE_BYTES ((A_H + B_H) * 2)
#define GEMM_SMEM (2 * STAGE_BYTES)

template <bool F4>
__global__ __launch_bounds__(NTHREADS, 1)
void gemm_tc_kernel(const float* __restrict__ Aext,
                    const float* __restrict__ Bw,
                    const float* __restrict__ bias,
                    const float* __restrict__ resid,
                    int a_sel, int out_sel, int mode, int do_lse,
                    int Kdim, int Nt, int row_shift) {
    extern __shared__ char smh[];
    const float* A   = (a_sel == 0) ? Aext : (a_sel == 1 ? g_h1 : g_h2);
    float*       Out = (out_sel == 1) ? g_h1 : (out_sel == 2 ? g_h2 : g_logits);

    int e   = blockIdx.z;
    int cnt = g_cnt[e];
    int m0  = blockIdx.x * TM;          // m fastest (grid-swap)
    if (m0 >= cnt) return;
    int n0  = blockIdx.y * TN;
    int mrem = cnt - m0;

    const float* Bexp = Bw + (size_t)e * Nt * Kdim;
    const int*   rows = g_rows[e];
    int tid = threadIdx.x, wid = tid >> 5, lane = tid & 31;
    uint32_t smem_base = smem_u32(smh);

    const int nch = (Kdim + BK - 1) / BK;

    auto brow_ptr = [&](int gn, bool& ok) -> const float* {
        if (mode == 1) {
            int f = gn >> 1;
            ok = (f < DFF_);
            size_t r = (gn & 1) ? (size_t)(DFF_ + f) : (size_t)f;
            return Bexp + r * Kdim;
        }
        ok = (gn < Nt);
        return Bexp + (size_t)gn * Kdim;
    };

    float4 ra4[2], rb4[4];
    float2 ra2[4], rb2[8];

    auto ldg_chunk = [&](int i) {
        int k0 = i * BK;
        if constexpr (F4) {
#pragma unroll
            for (int j = 0; j < 2; j++) {
                int u = tid + j * NTHREADS;
                int r = u >> 3, c = u & 7, kg = k0 + c * 4;
                int gm = m0 + r;
                float4 v = make_float4(0.f, 0.f, 0.f, 0.f);
                if (gm < cnt) {
                    int pr = rows[gm];
                    int rr = row_shift ? (pr >> 1) : pr;
                    v = *(const float4*)(A + (size_t)rr * Kdim + kg);
                }
                ra4[j] = v;
            }
#pragma unroll
            for (int j = 0; j < 4; j++) {
                int u = tid + j * NTHREADS;
                int r = u >> 3, c = u & 7, kg = k0 + c * 4;
                bool ok; const float* src = brow_ptr(n0 + r, ok);
                float4 v = make_float4(0.f, 0.f, 0.f, 0.f);
                if (ok) v = *(const float4*)(src + kg);
                rb4[j] = v;
            }
        } else {
#pragma unroll
            for (int j = 0; j < 4; j++) {
                int u = tid + j * NTHREADS;
                int r = u >> 4, c = u & 15, kg = k0 + c * 2;
                int gm = m0 + r;
                float2 v = make_float2(0.f, 0.f);
                if (gm < cnt && kg < Kdim) {
                    int pr = rows[gm];
                    int rr = row_shift ? (pr >> 1) : pr;
                    v = *(const float2*)(A + (size_t)rr * Kdim + kg);
                }
                ra2[j] = v;
            }
#pragma unroll
            for (int j = 0; j < 8; j++) {
                int u = tid + j * NTHREADS;
                int r = u >> 4, c = u & 15, kg = k0 + c * 2;
                bool ok; const float* src = brow_ptr(n0 + r, ok);
                float2 v = make_float2(0.f, 0.f);
                if (ok && kg < Kdim) v = *(const float2*)(src + kg);
                rb2[j] = v;
            }
        }
    };

    auto sts_chunk = [&](int sbuf) {
        uint32_t base = smem_base + (uint32_t)sbuf * STAGE_BYTES;
        if constexpr (F4) {
#pragma unroll
            for (int j = 0; j < 2; j++) {
                int u = tid + j * NTHREADS;
                int r = u >> 3, c = u & 7;
                uint32_t off = base + (uint32_t)(r * LDH + c * 4) * 2u;
                STS64(off, packbf(ra4[j].x, ra4[j].y), packbf(ra4[j].z, ra4[j].w));
            }
#pragma unroll
            for (int j = 0; j < 4; j++) {
                int u = tid + j * NTHREADS;
                int r = u >> 3, c = u & 7;
                uint32_t off = base + A_BYTES + (uint32_t)(r * LDH + c * 4) * 2u;
                STS64(off, packbf(rb4[j].x, rb4[j].y), packbf(rb4[j].z, rb4[j].w));
            }
        } else {
#pragma unroll
            for (int j = 0; j < 4; j++) {
                int u = tid + j * NTHREADS;
                int r = u >> 4, c = u & 15;
                uint32_t off = base + (uint32_t)(r * LDH + c * 2) * 2u;
                STS32(off, packbf(ra2[j].x, ra2[j].y));
            }
#pragma unroll
            for (int j = 0; j < 8; j++) {
                int u = tid + j * NTHREADS;
                int r = u >> 4, c = u & 15;
                uint32_t off = base + A_BYTES + (uint32_t)(r * LDH + c * 2) * 2u;
                STS32(off, packbf(rb2[j].x, rb2[j].y));
            }
        }
    };

    // warp layout: 2 (m) x 8 (n); warp tile 64 x 32
    int wy = wid >> 3, wx = wid & 7;
    int mw = wy * 64, nw = wx * 32;
    int lr = lane >> 2, lc = lane & 3;

    bool mlive[4];
#pragma unroll
    for (int mt = 0; mt < 4; mt++) mlive[mt] = (mw + mt * 16) < mrem;

    int lj = lane >> 3;
    int lrow = lane & 7;

    float acc[4][4][4];
#pragma unroll
    for (int i = 0; i < 4; i++)
#pragma unroll
        for (int j = 0; j < 4; j++)
#pragma unroll
            for (int q = 0; q < 4; q++) acc[i][j][q] = 0.f;

    // prologue
    ldg_chunk(0);
    sts_chunk(0);
    if (nch > 1) ldg_chunk(1);

    for (int it = 0; it < nch; it++) {
        __syncthreads();     // covers: sts(it) visible; all warps done compute(it-1)
        if (it + 1 < nch) sts_chunk((it + 1) & 1);
        if (it + 2 < nch) ldg_chunk(it + 2);

        uint32_t Au = smem_base + (uint32_t)(it & 1) * STAGE_BYTES;
        uint32_t Bu = Au + A_BYTES;
#pragma unroll
        for (int ks = 0; ks < BK; ks += 16) {
            uint32_t bfr[2][4];
#pragma unroll
            for (int kh = 0; kh < 2; kh++) {
                uint32_t addr = Bu + (uint32_t)((nw + lj * 8 + lrow) * LDH + ks + kh * 8) * 2u;
                LDSM_X4(bfr[kh][0], bfr[kh][1], bfr[kh][2], bfr[kh][3], addr);
            }
#pragma unroll
            for (int mt = 0; mt < 4; mt++) {
                if (!mlive[mt]) continue;
                uint32_t addr = Au + (uint32_t)((mw + mt * 16 + (lj & 1) * 8 + lrow) * LDH
                                                + ks + (lj >> 1) * 8) * 2u;
                uint32_t af[4];
                LDSM_X4(af[0], af[1], af[2], af[3], addr);
#pragma unroll
                for (int nt = 0; nt < 4; nt++) {
                    uint32_t bb[2] = { bfr[0][nt], bfr[1][nt] };
                    mma_bf16(acc[mt][nt], af, bb);
                }
            }
        }
    }

    __syncthreads();

    // ---- epilogue: store ----
    if (mode == 1) {
        const float* bb = bias + (size_t)e * DFF2_;
#pragma unroll
        for (int mt = 0; mt < 4; mt++) {
            if (!mlive[mt]) continue;
#pragma unroll
            for (int half = 0; half < 2; half++) {
                int rg = m0 + mw + mt * 16 + lr + half * 8;
                if (rg >= cnt) continue;
                int pair = rows[rg];
                size_t obase = (size_t)pair * DFF_;
#pragma unroll
                for (int nt = 0; nt < 4; nt++) {
                    int cg = n0 + nw + nt * 8 + 2 * lc;
                    int f  = cg >> 1;
                    if (f >= DFF_) continue;
                    float h = acc[mt][nt][half * 2 + 0] + bb[f];
                    float g = acc[mt][nt][half * 2 + 1] + bb[DFF_ + f];
                    float ge = 0.5f * g * (1.f + erff(g * 0.70710678118654752440f));
                    Out[obase + f] = h * ge;
                }
            }
        }
    } else {
        const float* bb = bias ? bias + (size_t)e * Nt : nullptr;
#pragma unroll
        for (int mt = 0; mt < 4; mt++) {
            if (!mlive[mt]) continue;
#pragma unroll
            for (int half = 0; half < 2; half++) {
                int rg = m0 + mw + mt * 16 + lr + half * 8;
                if (rg >= cnt) continue;
                int pair = rows[rg];
                size_t obase = (size_t)pair * Nt;
                const float* rr = resid ? resid + (size_t)(pair >> 1) * Nt : nullptr;
#pragma unroll
                for (int nt = 0; nt < 4; nt++) {
                    int cg = n0 + nw + nt * 8 + 2 * lc;
#pragma unroll
                    for (int q = 0; q < 2; q++) {
                        int col = cg + q;
                        if (col >= Nt) continue;
                        float v = acc[mt][nt][half * 2 + q];
                        if (bb) v += bb[col];
                        if (rr) v += rr[col];
                        Out[obase + col] = v;
                    }
                }
            }
        }
    }

    // ---- fused per-row online LSE from accumulators (proj only) ----
    if (do_lse) {
        float2* red = (float2*)smh;   // [8 wx][128 rows] = 8KB, GEMM smem reused
#pragma unroll
        for (int mt = 0; mt < 4; mt++) {
#pragma unroll
            for (int half = 0; half < 2; half++) {
                float m = -INFINITY, s = 0.f;
#pragma unroll
                for (int nt = 0; nt < 4; nt++) {
#pragma unroll
                    for (int q = 0; q < 2; q++) {
                        int col = n0 + nw + nt * 8 + 2 * lc + q;
                        if (col >= Nt) continue;
                        float xv = acc[mt][nt][half * 2 + q];
                        if (xv > m) { s = s * expf(m - xv) + 1.f; m = xv; }
                        else        { s += expf(xv - m); }
                    }
                }
                // reduce over the 4 lanes sharing this row (lane = lr*4 + lc)
#pragma unroll
                for (int off = 1; off <= 2; off <<= 1) {
                    float m2 = __shfl_xor_sync(0xffffffffu, m, off);
                    float s2 = __shfl_xor_sync(0xffffffffu, s, off);
                    float mm = fmaxf(m, m2);
                    s = s * expf(m - mm) + s2 * expf(m2 - mm);
                    m = mm;
                }
                if (lc == 0) {
                    int ridx = wy * 64 + mt * 16 + half * 8 + lr;
                    red[wx * 128 + ridx] = make_float2(m, s);
                }
            }
        }
        __syncthreads();
        if (tid < 128) {
            int row = tid;
            if (m0 + row < cnt) {
                float m = -INFINITY, s = 0.f;
#pragma unroll
                for (int w = 0; w < 8; w++) {
                    float2 v = red[w * 128 + row];
                    float mm = fmaxf(m, v.x);
                    s = s * expf(m - mm) + v.y * expf(v.x - mm);
                    m = mm;
                }
                lse_atomic_merge(rows[m0 + row], m, s);
            }
        }
    }
}

// ------------------------- combine two experts per token ---------------------
__global__ void combine_kernel(float* __restrict__ out) {
    size_t idx = (size_t)blockIdx.x * blockDim.x + threadIdx.x;
    const size_t total = (size_t)S_ * VOCAB_;
    if (idx >= total) return;
    int s = (int)(idx / VOCAB_);
    int v = (int)(idx % VOCAB_);
    int p0 = 2 * s, p1 = 2 * s + 1;
    unsigned long long e0 = g_mlse[p0], e1 = g_mlse[p1];
    float l0 = __uint_as_float((unsigned)(e0 & 0xffffffffull))
             + logf(__uint_as_float((unsigned)(e0 >> 32)));
    float l1 = __uint_as_float((unsigned)(e1 & 0xffffffffull))
             + logf(__uint_as_float((unsigned)(e1 >> 32)));
    float a0 = g_logits[(size_t)p0 * VOCAB_ + v] + g_gate[p0] - l0;
    float a1 = g_logits[(size_t)p1 * VOCAB_ + v] + g_gate[p1] - l1;
    float m = fmaxf(a0, a1);
    out[idx] = m + logf(expf(a0 - m) + expf(a1 - m));
}

// ------------------------- launch -------------------------
extern "C" void kernel_launch(void* const* d_in, const int* in_sizes, int n_in,
                              void* d_out, int out_size) {
    const float *x = nullptr, *Wr = nullptr, *Wup = nullptr,
                *bup = nullptr, *Wdown = nullptr, *Wproj = nullptr;
    for (int i = 0; i < n_in; i++) {
        const float* p = (const float*)d_in[i];
        switch (in_sizes[i]) {
            case S_ * DIM_:            x     = p; break;
            case E_ * DIM_:            Wr    = p; break;
            case E_ * DFF2_ * DIM_:    Wup   = p; break;
            case E_ * DFF2_:           bup   = p; break;
            case E_ * DIM_ * DFF_:     Wdown = p; break;
            case E_ * VOCAB_ * DIM_:   Wproj = p; break;
        }
    }
    if (!x)     x     = (const float*)d_in[0];
    if (!Wr)    Wr    = (const float*)d_in[1];
    if (!Wup)   Wup   = (const float*)d_in[2];
    if (!bup)   bup   = (const float*)d_in[3];
    if (!Wdown) Wdown = (const float*)d_in[4];
    if (!Wproj) Wproj = (const float*)d_in[5];
    float* out = (float*)d_out;

    cudaFuncSetAttribute(gemm_tc_kernel<true>,
                         cudaFuncAttributeMaxDynamicSharedMemorySize, GEMM_SMEM);
    cudaFuncSetAttribute(gemm_tc_kernel<false>,
                         cudaFuncAttributeMaxDynamicSharedMemorySize, GEMM_SMEM);

    // 1) router + fused grouping + lse reset
    router_kernel<<<S_, 256>>>(x, Wr);

    // 2) up + fused SwiGLU (K=1024 -> F4); grid: m fastest
    {
        dim3 grid((NPAIR + TM - 1) / TM, (DFF2_ + TN - 1) / TN, E_);
        gemm_tc_kernel<true><<<grid, NTHREADS, GEMM_SMEM>>>(x, Wup, bup, nullptr,
                                                            0, 1, 1, 0, DIM_, DFF2_, 1);
    }
    // 3) down + residual (K=2730 -> F2)
    {
        dim3 grid((NPAIR + TM - 1) / TM, (DIM_ + TN - 1) / TN, E_);
        gemm_tc_kernel<false><<<grid, NTHREADS, GEMM_SMEM>>>(nullptr, Wdown, nullptr, x,
                                                             1, 2, 0, 0, DFF_, DIM_, 0);
    }
    // 4) proj + fused LSE (K=1024 -> F4)   <-- ncu capture slot (#4)
    {
        dim3 grid((NPAIR + TM - 1) / TM, (VOCAB_ + TN - 1) / TN, E_);
        gemm_tc_kernel<true><<<grid, NTHREADS, GEMM_SMEM>>>(nullptr, Wproj, nullptr, nullptr,
                                                            2, 3, 0, 1, DIM_, VOCAB_, 0);
    }
    // 5) combine
    {
        size_t total = (size_t)S_ * VOCAB_;
        combine_kernel<<<(int)((total + 255) / 256), 256>>>(out);
    }
}